// round 9
// baseline (speedup 1.0000x reference)
#include <cuda_runtime.h>
#include <cstdint>

static constexpr int NB   = 8;
static constexpr int NN   = 384;
static constexpr int NF   = 64;
static constexpr int NT   = 192;
static constexpr int NS   = 5;
static constexpr int NSRC = 383;
static constexpr int NE   = 55200;
static constexpr int ETOT = NB * NE;        // 441600
static constexpr int CH   = 128;
static constexpr int NBLK = ETOT / CH;      // 3450

static constexpr int VSTR = 136;

// ---------------- global scratch ----------------
__device__ float g_P [NB * NN * NF];
__device__ float g_Qt[NB * NF * NN];
__device__ float g_logits[NB * NT * NN];
__device__ float g_Whi[4096];               // tf32 A-fragments
__device__ float g_W2f[4096];               // g1-folded W2 [j][o] (exact refine)
__device__ float g_Go[64], g_Co[64], g_Gw[64];
__device__ float g_scal[2];

__device__ __forceinline__ float tf32r(float x) {
    uint32_t u;
    asm("cvt.rna.tf32.f32 %0, %1;" : "=r"(u) : "f"(x));
    return __uint_as_float(u);
}

#define MMA_TF32(dd, av, b0, b1) \
    asm volatile("mma.sync.aligned.m16n8k8.row.col.f32.tf32.tf32.f32 " \
        "{%0,%1,%2,%3}, {%4,%5,%6,%7}, {%8,%9}, {%0,%1,%2,%3};" \
        : "+f"((dd)[0]), "+f"((dd)[1]), "+f"((dd)[2]), "+f"((dd)[3]) \
        : "r"(__float_as_uint((av).x)), "r"(__float_as_uint((av).y)), \
          "r"(__float_as_uint((av).z)), "r"(__float_as_uint((av).w)), \
          "r"(b0), "r"(b1))

#define ROWOFF(kk) ((kk) * 192 + (((kk) * ((kk) - 1)) >> 1))

// ---------------------------------------------------------------------------
// Kernel 1: prep — blocks 0..191 projection, block 192 constant setup
// ---------------------------------------------------------------------------
__global__ __launch_bounds__(256) void prep_kernel(
    const float* __restrict__ nodes, const float* __restrict__ w1,
    const float* __restrict__ b1,    const float* __restrict__ w2,
    const float* __restrict__ g1,    const float* __restrict__ be1,
    const float* __restrict__ b2,    const float* __restrict__ g2,
    const float* __restrict__ be2,   const float* __restrict__ w3,
    const float* __restrict__ b3)
{
    __shared__ float sW[128 * 64];
    __shared__ float sNd[16 * 64];
    const int tid = threadIdx.x;

    if (blockIdx.x < 192) {
        // ---- projection ----
        for (int i = tid; i < 128 * 64; i += 256) sW[i] = w1[i];
        const int n0 = blockIdx.x * 16;
        for (int i = tid; i < 16 * 64; i += 256) sNd[i] = nodes[n0 * 64 + i];
        __syncthreads();

        const int nl = tid >> 4;
        const int og = tid & 15;
        const bool isP = og < 8;
        const int colb = (og & 7) * 8;

        float acc[8];
#pragma unroll
        for (int i = 0; i < 8; ++i) acc[i] = 0.f;
        const float* nd = &sNd[nl * 64];
        const float* wp = sW + (isP ? 0 : 64 * 64) + colb;
#pragma unroll 16
        for (int f = 0; f < 64; ++f) {
            float x = nd[f];
            const float4* w4 = (const float4*)(wp + f * 64);
            float4 a = w4[0], bq = w4[1];
            acc[0] = fmaf(x, a.x, acc[0]);  acc[1] = fmaf(x, a.y, acc[1]);
            acc[2] = fmaf(x, a.z, acc[2]);  acc[3] = fmaf(x, a.w, acc[3]);
            acc[4] = fmaf(x, bq.x, acc[4]); acc[5] = fmaf(x, bq.y, acc[5]);
            acc[6] = fmaf(x, bq.z, acc[6]); acc[7] = fmaf(x, bq.w, acc[7]);
        }
        const int gn = n0 + nl;
        if (isP) {
#pragma unroll
            for (int i = 0; i < 8; ++i)
                g_P[gn * 64 + colb + i] = acc[i] + b1[colb + i];
        } else {
            const int bb = gn / NN, n = gn % NN;
#pragma unroll
            for (int i = 0; i < 8; ++i)
                g_Qt[((size_t)bb * 64 + colb + i) * NN + n] = acc[i];
        }
    } else {
        // ---- constant setup ----
        for (int t = tid; t < 1024; t += 256) {
            int s = t >> 7, om = (t >> 5) & 3, lane = t & 31;
            int g = lane >> 2, tig = lane & 3;
            int o1 = om * 16 + g, o2 = o1 + 8;
            int j1 = 8 * s + tig, j2 = j1 + 4;
            g_Whi[t * 4 + 0] = tf32r(g1[j1] * w2[j1 * 64 + o1]);
            g_Whi[t * 4 + 1] = tf32r(g1[j1] * w2[j1 * 64 + o2]);
            g_Whi[t * 4 + 2] = tf32r(g1[j2] * w2[j2 * 64 + o1]);
            g_Whi[t * 4 + 3] = tf32r(g1[j2] * w2[j2 * 64 + o2]);
#pragma unroll
            for (int q = 0; q < 4; ++q) {
                int i = t * 4 + q;
                g_W2f[i] = g1[i >> 6] * w2[i];
            }
        }
        if (tid < 64) {
            float G = 0.f, C = b2[tid];
            for (int j = 0; j < 64; ++j) {
                G += g1[j] * w2[j * 64 + tid];
                C = fmaf(be1[j], w2[j * 64 + tid], C);
            }
            g_Go[tid] = G;
            g_Co[tid] = C;
            g_Gw[tid] = g2[tid] * w3[tid];
        }
        if (tid == 0) {
            float gs = 0.f, cc = b3[0];
            for (int o = 0; o < 64; ++o) { gs += g2[o] * w3[o]; cc = fmaf(be2[o], w3[o], cc); }
            g_scal[0] = gs;
            g_scal[1] = cc;
        }
    }
}

// ---------------------------------------------------------------------------
// Kernel 2: edge MLP — single-pass TF32 mma.sync, P rows staged in smem
// ---------------------------------------------------------------------------
static constexpr int SVH = 0;                 // 64*VSTR
static constexpr int SRS = SVH + 64 * VSTR;   // 128
static constexpr int SMU = SRS + 128;
static constexpr int SP1 = SMU + 128;
static constexpr int SP2 = SP1 + 128;
static constexpr int SR1 = SP2 + 128;
static constexpr int SRQ = SR1 + 128;
static constexpr int SR3 = SRQ + 128;
static constexpr int SGO = SR3 + 128;         // 64
static constexpr int SCO = SGO + 64;
static constexpr int SGW = SCO + 64;
static constexpr int SOF = SGW + 64;          // 128 int
static constexpr int SSC = SOF + 128;         // 2
static constexpr int SPA = SSC + 2;           // 128 (two P rows)
static constexpr int SRW = SPA + 128;         // 2 int row ids
static constexpr int SMEM_FLOATS = SRW + 2;
static constexpr int SMEM_BYTES = SMEM_FLOATS * 4;

__global__ __launch_bounds__(256, 3) void mlp_kernel() {
    extern __shared__ float sm[];
    const int tid  = threadIdx.x;
    const int lane = tid & 31;
    const int wid  = tid >> 5;

    if (tid < 64) {
        sm[SGO + tid] = g_Go[tid];
        sm[SCO + tid] = g_Co[tid];
        sm[SGW + tid] = g_Gw[tid];
    }
    if (tid == 0) { sm[SSC] = g_scal[0]; sm[SSC + 1] = g_scal[1]; }

    // ---- decode ----
    const int el = tid & 127;
    const int kh = tid >> 7;
    const int k0 = kh * 32;
    const int E  = blockIdx.x * CH + el;
    const int b  = E / NE;
    const int eb = E - b * NE;
    int k = (int)floorf(-191.5f + sqrtf(36672.25f + 2.0f * (float)eb));
    k = max(0, min(NT - 1, k));
    while (k < NT - 1 && ROWOFF(k + 1) <= eb) ++k;
    while (k > 0 && ROWOFF(k) > eb) --k;
    const int c = eb - ROWOFF(k);
    const int r = k + NT;
    const int myrow = b * NN + r;
    if (kh == 0) {
        ((int*)sm)[SOF + el] = (b * NT + k) * NN + c;
        if (el == 0)   ((int*)sm)[SRW]     = myrow;
        if (el == 127) ((int*)sm)[SRW + 1] = myrow;
    }
    __syncthreads();

    // stage the (<=2) P rows this block touches
    if (tid < 128) {
        int rowid = ((int*)sm)[SRW + (tid >> 6)];
        sm[SPA + tid] = g_P[(size_t)rowid * 64 + (tid & 63)];
    }
    __syncthreads();

    // ---- phase A ----
    {
        const int pbase = SPA + ((myrow == ((int*)sm)[SRW]) ? 0 : 64) + k0;
        const float* qp = g_Qt + ((size_t)(b * 64 + k0)) * NN + c;
        float s1 = 0.f, s2 = 0.f;
#pragma unroll
        for (int j = 0; j < 32; ++j) {
            float v = fmaxf(sm[pbase + j] + qp[j * NN], 0.f);
            s1 += v;
            s2 = fmaf(v, v, s2);
            sm[SVH + (k0 + j) * VSTR + el] = tf32r(v);
        }
        if (kh) { sm[SP1 + el] = s1; sm[SP2 + el] = s2; }
        __syncthreads();
        if (!kh) {
            s1 += sm[SP1 + el];
            s2 += sm[SP2 + el];
            const float inv = 1.f / 64.f;
            float mu   = s1 * inv;
            float rstd = rsqrtf(fmaf(-mu, mu, s2 * inv) + 1e-5f);
            sm[SRS + el] = rstd;
            sm[SMU + el] = mu * rstd;
        }
    }
    __syncthreads();

    // ---- phase B: single-pass mma ----
    const int g     = lane >> 2;
    const int tig   = lane & 3;
    const int ohalf = wid >> 2;
    const int eb0   = (wid & 3) * 32;

    float d[2][4][4];
#pragma unroll
    for (int mt = 0; mt < 2; ++mt)
#pragma unroll
        for (int nt = 0; nt < 4; ++nt)
#pragma unroll
            for (int q = 0; q < 4; ++q) d[mt][nt][q] = 0.f;

    const float4* WH = (const float4*)g_Whi;

#pragma unroll
    for (int s = 0; s < 8; ++s) {
        const int row0 = (8 * s + tig) * VSTR;
        const int row1 = row0 + 4 * VSTR;
        uint32_t b0[4], b1[4];
#pragma unroll
        for (int nt = 0; nt < 4; ++nt) {
            int col = eb0 + nt * 8 + g;
            b0[nt] = __float_as_uint(sm[SVH + row0 + col]);
            b1[nt] = __float_as_uint(sm[SVH + row1 + col]);
        }
        float4 ah0 = WH[(s * 4 + ohalf * 2 + 0) * 32 + lane];
        float4 ah1 = WH[(s * 4 + ohalf * 2 + 1) * 32 + lane];
#pragma unroll
        for (int nt = 0; nt < 4; ++nt) {
            MMA_TF32(d[0][nt], ah0, b0[nt], b1[nt]);
            MMA_TF32(d[1][nt], ah1, b0[nt], b1[nt]);
        }
    }

    // ---- epilogue ----
    const int ob = ohalf * 32;
    const float Go0 = sm[SGO + ob + g],      Co0 = sm[SCO + ob + g],      Gw0 = sm[SGW + ob + g];
    const float Go1 = sm[SGO + ob + g + 8],  Co1 = sm[SCO + ob + g + 8],  Gw1 = sm[SGW + ob + g + 8];
    const float Go2 = sm[SGO + ob + g + 16], Co2 = sm[SCO + ob + g + 16], Gw2 = sm[SGW + ob + g + 16];
    const float Go3 = sm[SGO + ob + g + 24], Co3 = sm[SCO + ob + g + 24], Gw3 = sm[SGW + ob + g + 24];

    float S1[4][2], SQ[4][2], S3[4][2];
#pragma unroll
    for (int nt = 0; nt < 4; ++nt)
#pragma unroll
        for (int h = 0; h < 2; ++h) {
            int ecol = eb0 + nt * 8 + 2 * tig + h;
            float rstd = sm[SRS + ecol];
            float mur  = sm[SMU + ecol];
            float h0 = fmaxf(fmaf(d[0][nt][h],     rstd, fmaf(-mur, Go0, Co0)), 0.f);
            float h1 = fmaxf(fmaf(d[0][nt][2 + h], rstd, fmaf(-mur, Go1, Co1)), 0.f);
            float h2 = fmaxf(fmaf(d[1][nt][h],     rstd, fmaf(-mur, Go2, Co2)), 0.f);
            float h3 = fmaxf(fmaf(d[1][nt][2 + h], rstd, fmaf(-mur, Go3, Co3)), 0.f);
            S1[nt][h] = h0 + h1 + h2 + h3;
            SQ[nt][h] = fmaf(h0, h0, fmaf(h1, h1, fmaf(h2, h2, h3 * h3)));
            S3[nt][h] = fmaf(h0, Gw0, fmaf(h1, Gw1, fmaf(h2, Gw2, h3 * Gw3)));
        }

#pragma unroll
    for (int m = 4; m <= 16; m <<= 1) {
#pragma unroll
        for (int nt = 0; nt < 4; ++nt)
#pragma unroll
            for (int h = 0; h < 2; ++h) {
                S1[nt][h] += __shfl_xor_sync(0xffffffffu, S1[nt][h], m);
                SQ[nt][h] += __shfl_xor_sync(0xffffffffu, SQ[nt][h], m);
                S3[nt][h] += __shfl_xor_sync(0xffffffffu, S3[nt][h], m);
            }
    }

    if (ohalf == 0 && g == 0) {
#pragma unroll
        for (int nt = 0; nt < 4; ++nt)
#pragma unroll
            for (int h = 0; h < 2; ++h) {
                int ecol = eb0 + nt * 8 + 2 * tig + h;
                sm[SR1 + ecol] = S1[nt][h];
                sm[SRQ + ecol] = SQ[nt][h];
                sm[SR3 + ecol] = S3[nt][h];
            }
    }
    __syncthreads();
    if (ohalf == 1 && g == 0) {
        const float gsum = sm[SSC], ccst = sm[SSC + 1];
        const float inv = 1.f / 64.f;
#pragma unroll
        for (int nt = 0; nt < 4; ++nt)
#pragma unroll
            for (int h = 0; h < 2; ++h) {
                int ecol = eb0 + nt * 8 + 2 * tig + h;
                float t1 = S1[nt][h] + sm[SR1 + ecol];
                float tq = SQ[nt][h] + sm[SRQ + ecol];
                float t3 = S3[nt][h] + sm[SR3 + ecol];
                float mu2   = t1 * inv;
                float rstd2 = rsqrtf(fmaf(-mu2, mu2, tq * inv) + 1e-5f);
                float logit = fmaf(rstd2, fmaf(-mu2, gsum, t3), ccst);
                g_logits[((int*)sm)[SOF + ecol]] = logit;
            }
    }
}

// ---------------------------------------------------------------------------
// Kernel 3: argmax with lazy exact-fp32 rescue of near-ties (window 0.06)
// ---------------------------------------------------------------------------
static constexpr float CAND_WIN = 0.06f;

__global__ __launch_bounds__(256) void argmax_kernel(
    const float* __restrict__ gumbel, float* __restrict__ out)
{
    __shared__ float sLog[NN];
    __shared__ float sSel[NN];
    __shared__ float sZ[NS * NN];
    __shared__ float sVc[NS * 64];
    __shared__ int   sCand[NS * 32];

    const int k = blockIdx.x;
    const int b = blockIdx.y;
    const int r = k + NT;
    const int nsrc = r;
    const int tid = threadIdx.x;
    const int wid = tid >> 5, lane = tid & 31;

    for (int c = tid; c < NN; c += 256) sSel[c] = 0.f;
    for (int c = tid; c < nsrc; c += 256)
        sLog[c] = g_logits[((size_t)b * NT + k) * NN + c];
    __syncthreads();

    if (wid < NS) {
        const float* gu = gumbel + (((size_t)wid * NB + b) * NT + k) * NSRC;
        const float NEGINF = -__int_as_float(0x7f800000);

        float best[4];
#pragma unroll
        for (int q = 0; q < 4; ++q) best[q] = NEGINF;
        for (int c0 = lane; c0 < nsrc; c0 += 128) {
#pragma unroll
            for (int q = 0; q < 4; ++q) {
                int cc = c0 + 32 * q;
                if (cc < nsrc) {
                    float z = sLog[cc] + gu[cc];
                    sZ[wid * NN + cc] = z;
                    best[q] = fmaxf(best[q], z);
                }
            }
        }
        float m = fmaxf(fmaxf(best[0], best[1]), fmaxf(best[2], best[3]));
#pragma unroll
        for (int off = 16; off; off >>= 1)
            m = fmaxf(m, __shfl_xor_sync(0xffffffffu, m, off));
        const float thr = m - CAND_WIN;
        __syncwarp();

        int cnt = 0;
        for (int c0 = 0; c0 < nsrc; c0 += 32) {
            int cc = c0 + lane;
            float z = (cc < nsrc) ? sZ[wid * NN + cc] : NEGINF;
            unsigned msk = __ballot_sync(0xffffffffu, z >= thr);
            if (lane == 0) {
                while (msk) {
                    int bit = __ffs(msk) - 1;
                    if (cnt < 32) sCand[wid * 32 + cnt] = c0 + bit;
                    ++cnt;
                    msk &= msk - 1;
                }
            }
        }
        cnt = __shfl_sync(0xffffffffu, cnt, 0);
        if (cnt > 32) cnt = 32;
        __syncwarp();

        int sel = sCand[wid * 32];
        if (cnt > 1) {
            // exact rescoring; weights/P read straight from global (L1/L2 hot, rare path)
            const float p0 = g_P[((size_t)b * NN + r) * 64 + lane];
            const float p1 = g_P[((size_t)b * NN + r) * 64 + 32 + lane];
            float bz = NEGINF;
            for (int q = 0; q < cnt; ++q) {
                int cc = sCand[wid * 32 + q];
                float q0 = g_Qt[((size_t)b * 64 + lane) * NN + cc];
                float q1 = g_Qt[((size_t)b * 64 + lane + 32) * NN + cc];
                float v0 = fmaxf(p0 + q0, 0.f);
                float v1 = fmaxf(p1 + q1, 0.f);
                sVc[wid * 64 + lane] = v0;
                sVc[wid * 64 + lane + 32] = v1;
                float s1 = v0 + v1;
                float s2 = fmaf(v0, v0, v1 * v1);
#pragma unroll
                for (int off = 16; off; off >>= 1) {
                    s1 += __shfl_xor_sync(0xffffffffu, s1, off);
                    s2 += __shfl_xor_sync(0xffffffffu, s2, off);
                }
                const float inv = 1.f / 64.f;
                float mu   = s1 * inv;
                float rstd = rsqrtf(fmaf(-mu, mu, s2 * inv) + 1e-5f);
                __syncwarp();
                float a0 = 0.f, a1 = 0.f;
#pragma unroll 8
                for (int j = 0; j < 64; ++j) {
                    float vv = sVc[wid * 64 + j];
                    a0 = fmaf(vv, g_W2f[j * 64 + lane], a0);
                    a1 = fmaf(vv, g_W2f[j * 64 + lane + 32], a1);
                }
                float mur = mu * rstd;
                float h0 = fmaxf(fmaf(rstd, a0, fmaf(-mur, g_Go[lane], g_Co[lane])), 0.f);
                float h1 = fmaxf(fmaf(rstd, a1, fmaf(-mur, g_Go[lane + 32], g_Co[lane + 32])), 0.f);
                float S1 = h0 + h1;
                float Sq = fmaf(h0, h0, h1 * h1);
                float S3 = fmaf(h0, g_Gw[lane], h1 * g_Gw[lane + 32]);
#pragma unroll
                for (int off = 16; off; off >>= 1) {
                    S1 += __shfl_xor_sync(0xffffffffu, S1, off);
                    Sq += __shfl_xor_sync(0xffffffffu, Sq, off);
                    S3 += __shfl_xor_sync(0xffffffffu, S3, off);
                }
                float mu2   = S1 * inv;
                float rstd2 = rsqrtf(fmaf(-mu2, mu2, Sq * inv) + 1e-5f);
                float lg    = fmaf(rstd2, fmaf(-mu2, g_scal[0], S3), g_scal[1]);
                float z     = lg + __ldg(&gu[cc]);
                if (z > bz) { bz = z; sel = cc; }
                __syncwarp();
            }
        }
        if (lane == 0) sSel[sel] = 1.f;
    }
    __syncthreads();

    float* rowR = out + ((size_t)b * NN + r) * NN;
    float* rowK = out + ((size_t)b * NN + k) * NN;
    for (int c = tid; c < NN; c += 256) {
        rowR[c] = sSel[c];
        rowK[c] = 0.f;
    }
}

// ---------------------------------------------------------------------------
extern "C" void kernel_launch(void* const* d_in, const int* in_sizes, int n_in,
                              void* d_out, int out_size) {
    const float* nodes  = (const float*)d_in[0];
    const float* w1     = (const float*)d_in[1];
    const float* b1     = (const float*)d_in[2];
    const float* g1     = (const float*)d_in[3];
    const float* be1    = (const float*)d_in[4];
    const float* w2     = (const float*)d_in[5];
    const float* b2     = (const float*)d_in[6];
    const float* g2     = (const float*)d_in[7];
    const float* be2    = (const float*)d_in[8];
    const float* w3     = (const float*)d_in[9];
    const float* b3     = (const float*)d_in[10];
    const float* gumbel = (const float*)d_in[11];

    cudaFuncSetAttribute(mlp_kernel,
                         cudaFuncAttributeMaxDynamicSharedMemorySize, SMEM_BYTES);

    prep_kernel<<<193, 256>>>(nodes, w1, b1, w2, g1, be1, b2, g2, be2, w3, b3);
    mlp_kernel<<<NBLK, 256, SMEM_BYTES>>>();
    dim3 grid3(NT, NB);
    argmax_kernel<<<grid3, 256>>>(gumbel, (float*)d_out);
}

// round 10
// speedup vs baseline: 1.0078x; 1.0078x over previous
#include <cuda_runtime.h>
#include <cstdint>

static constexpr int NB   = 8;
static constexpr int NN   = 384;
static constexpr int NF   = 64;
static constexpr int NT   = 192;
static constexpr int NS   = 5;
static constexpr int NSRC = 383;
static constexpr int NE   = 55200;
static constexpr int ETOT = NB * NE;        // 441600
static constexpr int CH   = 128;
static constexpr int NBLK = ETOT / CH;      // 3450

static constexpr int VSTR = 136;            // conflict-free B-fragment stride

// ---------------- global scratch ----------------
__device__ float g_P [NB * NN * NF];
__device__ float g_Qt[NB * NF * NN];
__device__ float g_logits[NB * NT * NN];    // single-pass tf32 approx
__device__ float g_Whi[4096];               // W2 A-fragments (tf32 hi)
__device__ float g_W2f[4096];               // g1-folded W2, [j][o] (exact refine)
__device__ float g_Go[64], g_Co[64], g_Gw[64];
__device__ float g_scal[2];

__device__ __forceinline__ float tf32r(float x) {
    uint32_t u;
    asm("cvt.rna.tf32.f32 %0, %1;" : "=r"(u) : "f"(x));
    return __uint_as_float(u);
}

#define MMA_TF32(dd, av, b0, b1) \
    asm volatile("mma.sync.aligned.m16n8k8.row.col.f32.tf32.tf32.f32 " \
        "{%0,%1,%2,%3}, {%4,%5,%6,%7}, {%8,%9}, {%0,%1,%2,%3};" \
        : "+f"((dd)[0]), "+f"((dd)[1]), "+f"((dd)[2]), "+f"((dd)[3]) \
        : "r"(__float_as_uint((av).x)), "r"(__float_as_uint((av).y)), \
          "r"(__float_as_uint((av).z)), "r"(__float_as_uint((av).w)), \
          "r"(b0), "r"(b1))

#define ROWOFF(kk) ((kk) * 192 + (((kk) * ((kk) - 1)) >> 1))

// ---------------------------------------------------------------------------
// Kernel 0: constants — tf32 A-fragments, exact folded weights, LN folds
// ---------------------------------------------------------------------------
__global__ void setup_kernel(const float* __restrict__ w2,
                             const float* __restrict__ g1,
                             const float* __restrict__ be1,
                             const float* __restrict__ b2,
                             const float* __restrict__ g2,
                             const float* __restrict__ be2,
                             const float* __restrict__ w3,
                             const float* __restrict__ b3) {
    int t = threadIdx.x;                  // 0..1023
    int s = t >> 7, om = (t >> 5) & 3, lane = t & 31;
    int g = lane >> 2, tig = lane & 3;
    int o1 = om * 16 + g, o2 = o1 + 8;
    int j1 = 8 * s + tig, j2 = j1 + 4;
    g_Whi[t * 4 + 0] = tf32r(g1[j1] * w2[j1 * 64 + o1]);
    g_Whi[t * 4 + 1] = tf32r(g1[j1] * w2[j1 * 64 + o2]);
    g_Whi[t * 4 + 2] = tf32r(g1[j2] * w2[j2 * 64 + o1]);
    g_Whi[t * 4 + 3] = tf32r(g1[j2] * w2[j2 * 64 + o2]);
#pragma unroll
    for (int q = 0; q < 4; ++q) {
        int i = t * 4 + q;                // [j][o]
        g_W2f[i] = g1[i >> 6] * w2[i];
    }
    if (t < 64) {
        float G = 0.f, C = b2[t];
        for (int j = 0; j < 64; ++j) {
            G += g1[j] * w2[j * 64 + t];
            C = fmaf(be1[j], w2[j * 64 + t], C);
        }
        g_Go[t] = G;
        g_Co[t] = C;
        g_Gw[t] = g2[t] * w3[t];
    }
    if (t == 0) {
        float gs = 0.f, cc = b3[0];
        for (int o = 0; o < 64; ++o) { gs += g2[o] * w3[o]; cc = fmaf(be2[o], w3[o], cc); }
        g_scal[0] = gs;
        g_scal[1] = cc;
    }
}

// ---------------------------------------------------------------------------
// Kernel 1: factored first-layer projection
// ---------------------------------------------------------------------------
__global__ __launch_bounds__(256) void proj_kernel(const float* __restrict__ nodes,
                                                   const float* __restrict__ w1,
                                                   const float* __restrict__ b1) {
    __shared__ float sW[128 * 64];
    __shared__ float sNd[16 * 64];
    const int tid = threadIdx.x;
    for (int i = tid; i < 128 * 64; i += 256) sW[i] = w1[i];
    const int n0 = blockIdx.x * 16;
    for (int i = tid; i < 16 * 64; i += 256) sNd[i] = nodes[n0 * 64 + i];
    __syncthreads();

    const int nl = tid >> 4;
    const int og = tid & 15;
    const bool isP = og < 8;
    const int colb = (og & 7) * 8;

    float acc[8];
#pragma unroll
    for (int i = 0; i < 8; ++i) acc[i] = 0.f;
    const float* nd = &sNd[nl * 64];
    const float* wp = sW + (isP ? 0 : 64 * 64) + colb;
#pragma unroll 16
    for (int f = 0; f < 64; ++f) {
        float x = nd[f];
        const float4* w4 = (const float4*)(wp + f * 64);
        float4 a = w4[0], bq = w4[1];
        acc[0] = fmaf(x, a.x, acc[0]);  acc[1] = fmaf(x, a.y, acc[1]);
        acc[2] = fmaf(x, a.z, acc[2]);  acc[3] = fmaf(x, a.w, acc[3]);
        acc[4] = fmaf(x, bq.x, acc[4]); acc[5] = fmaf(x, bq.y, acc[5]);
        acc[6] = fmaf(x, bq.z, acc[6]); acc[7] = fmaf(x, bq.w, acc[7]);
    }
    const int gn = n0 + nl;
    if (isP) {
#pragma unroll
        for (int i = 0; i < 8; ++i)
            g_P[gn * 64 + colb + i] = acc[i] + b1[colb + i];
    } else {
        const int bb = gn / NN, n = gn % NN;
#pragma unroll
        for (int i = 0; i < 8; ++i)
            g_Qt[((size_t)bb * 64 + colb + i) * NN + n] = acc[i];
    }
}

// ---------------------------------------------------------------------------
// Kernel 2: edge MLP — single-pass TF32 mma.sync (R7 structure)
// ---------------------------------------------------------------------------
static constexpr int SVH = 0;                 // 64*VSTR
static constexpr int SRS = SVH + 64 * VSTR;   // 128 rstd
static constexpr int SMU = SRS + 128;
static constexpr int SP1 = SMU + 128;
static constexpr int SP2 = SP1 + 128;
static constexpr int SR1 = SP2 + 128;
static constexpr int SRQ = SR1 + 128;
static constexpr int SR3 = SRQ + 128;
static constexpr int SGO = SR3 + 128;         // 64
static constexpr int SCO = SGO + 64;
static constexpr int SGW = SCO + 64;
static constexpr int SOF = SGW + 64;          // 128 int
static constexpr int SSC = SOF + 128;
static constexpr int SMEM_FLOATS = SSC + 2;
static constexpr int SMEM_BYTES = SMEM_FLOATS * 4;

__global__ __launch_bounds__(256, 3) void mlp_kernel() {
    extern __shared__ float sm[];
    const int tid  = threadIdx.x;
    const int lane = tid & 31;
    const int wid  = tid >> 5;

    if (tid < 64) {
        sm[SGO + tid] = g_Go[tid];
        sm[SCO + tid] = g_Co[tid];
        sm[SGW + tid] = g_Gw[tid];
    }
    if (tid == 0) { sm[SSC] = g_scal[0]; sm[SSC + 1] = g_scal[1]; }

    // ---- phase A: 2 threads per edge ----
    const int el = tid & 127;
    const int kh = tid >> 7;
    const int k0 = kh * 32;
    const int E  = blockIdx.x * CH + el;
    const int b  = E / NE;
    const int eb = E - b * NE;
    int k = (int)floorf(-191.5f + sqrtf(36672.25f + 2.0f * (float)eb));
    k = max(0, min(NT - 1, k));
    while (k < NT - 1 && ROWOFF(k + 1) <= eb) ++k;
    while (k > 0 && ROWOFF(k) > eb) --k;
    const int c = eb - ROWOFF(k);
    const int r = k + NT;
    if (kh == 0) ((int*)sm)[SOF + el] = (b * NT + k) * NN + c;

    {
        const float* pp = g_P + ((size_t)(b * NN + r)) * 64 + k0;
        const float* qp = g_Qt + ((size_t)(b * 64 + k0)) * NN + c;
        float pv[32];
        const float4* p4 = (const float4*)pp;
#pragma unroll
        for (int i = 0; i < 8; ++i) {
            float4 t4 = p4[i];
            pv[4 * i] = t4.x; pv[4 * i + 1] = t4.y; pv[4 * i + 2] = t4.z; pv[4 * i + 3] = t4.w;
        }
        float s1 = 0.f, s2 = 0.f;
#pragma unroll
        for (int j = 0; j < 32; ++j) {
            float v = fmaxf(pv[j] + qp[j * NN], 0.f);
            s1 += v;
            s2 = fmaf(v, v, s2);
            sm[SVH + (k0 + j) * VSTR + el] = tf32r(v);
        }
        if (kh) { sm[SP1 + el] = s1; sm[SP2 + el] = s2; }
        __syncthreads();
        if (!kh) {
            s1 += sm[SP1 + el];
            s2 += sm[SP2 + el];
            const float inv = 1.f / 64.f;
            float mu   = s1 * inv;
            float rstd = rsqrtf(fmaf(-mu, mu, s2 * inv) + 1e-5f);
            sm[SRS + el] = rstd;
            sm[SMU + el] = mu * rstd;
        }
    }
    __syncthreads();

    // ---- phase B: single-pass mma ----
    const int g     = lane >> 2;
    const int tig   = lane & 3;
    const int ohalf = wid >> 2;
    const int eb0   = (wid & 3) * 32;

    float d[2][4][4];
#pragma unroll
    for (int mt = 0; mt < 2; ++mt)
#pragma unroll
        for (int nt = 0; nt < 4; ++nt)
#pragma unroll
            for (int q = 0; q < 4; ++q) d[mt][nt][q] = 0.f;

    const float4* WH = (const float4*)g_Whi;

#pragma unroll
    for (int s = 0; s < 8; ++s) {
        const int row0 = (8 * s + tig) * VSTR;
        const int row1 = row0 + 4 * VSTR;
        uint32_t b0[4], b1[4];
#pragma unroll
        for (int nt = 0; nt < 4; ++nt) {
            int col = eb0 + nt * 8 + g;
            b0[nt] = __float_as_uint(sm[SVH + row0 + col]);
            b1[nt] = __float_as_uint(sm[SVH + row1 + col]);
        }
        float4 ah0 = WH[(s * 4 + ohalf * 2 + 0) * 32 + lane];
        float4 ah1 = WH[(s * 4 + ohalf * 2 + 1) * 32 + lane];
#pragma unroll
        for (int nt = 0; nt < 4; ++nt) {
            MMA_TF32(d[0][nt], ah0, b0[nt], b1[nt]);
            MMA_TF32(d[1][nt], ah1, b0[nt], b1[nt]);
        }
    }

    // ---- epilogue ----
    const int ob = ohalf * 32;
    const float Go0 = sm[SGO + ob + g],      Co0 = sm[SCO + ob + g],      Gw0 = sm[SGW + ob + g];
    const float Go1 = sm[SGO + ob + g + 8],  Co1 = sm[SCO + ob + g + 8],  Gw1 = sm[SGW + ob + g + 8];
    const float Go2 = sm[SGO + ob + g + 16], Co2 = sm[SCO + ob + g + 16], Gw2 = sm[SGW + ob + g + 16];
    const float Go3 = sm[SGO + ob + g + 24], Co3 = sm[SCO + ob + g + 24], Gw3 = sm[SGW + ob + g + 24];

    float S1[4][2], SQ[4][2], S3[4][2];
#pragma unroll
    for (int nt = 0; nt < 4; ++nt)
#pragma unroll
        for (int h = 0; h < 2; ++h) {
            int ecol = eb0 + nt * 8 + 2 * tig + h;
            float rstd = sm[SRS + ecol];
            float mur  = sm[SMU + ecol];
            float h0 = fmaxf(fmaf(d[0][nt][h],     rstd, fmaf(-mur, Go0, Co0)), 0.f);
            float h1 = fmaxf(fmaf(d[0][nt][2 + h], rstd, fmaf(-mur, Go1, Co1)), 0.f);
            float h2 = fmaxf(fmaf(d[1][nt][h],     rstd, fmaf(-mur, Go2, Co2)), 0.f);
            float h3 = fmaxf(fmaf(d[1][nt][2 + h], rstd, fmaf(-mur, Go3, Co3)), 0.f);
            S1[nt][h] = h0 + h1 + h2 + h3;
            SQ[nt][h] = fmaf(h0, h0, fmaf(h1, h1, fmaf(h2, h2, h3 * h3)));
            S3[nt][h] = fmaf(h0, Gw0, fmaf(h1, Gw1, fmaf(h2, Gw2, h3 * Gw3)));
        }

#pragma unroll
    for (int m = 4; m <= 16; m <<= 1) {
#pragma unroll
        for (int nt = 0; nt < 4; ++nt)
#pragma unroll
            for (int h = 0; h < 2; ++h) {
                S1[nt][h] += __shfl_xor_sync(0xffffffffu, S1[nt][h], m);
                SQ[nt][h] += __shfl_xor_sync(0xffffffffu, SQ[nt][h], m);
                S3[nt][h] += __shfl_xor_sync(0xffffffffu, S3[nt][h], m);
            }
    }

    if (ohalf == 0 && g == 0) {
#pragma unroll
        for (int nt = 0; nt < 4; ++nt)
#pragma unroll
            for (int h = 0; h < 2; ++h) {
                int ecol = eb0 + nt * 8 + 2 * tig + h;
                sm[SR1 + ecol] = S1[nt][h];
                sm[SRQ + ecol] = SQ[nt][h];
                sm[SR3 + ecol] = S3[nt][h];
            }
    }
    __syncthreads();
    if (ohalf == 1 && g == 0) {
        const float gsum = sm[SSC], ccst = sm[SSC + 1];
        const float inv = 1.f / 64.f;
#pragma unroll
        for (int nt = 0; nt < 4; ++nt)
#pragma unroll
            for (int h = 0; h < 2; ++h) {
                int ecol = eb0 + nt * 8 + 2 * tig + h;
                float t1 = S1[nt][h] + sm[SR1 + ecol];
                float tq = SQ[nt][h] + sm[SRQ + ecol];
                float t3 = S3[nt][h] + sm[SR3 + ecol];
                float mu2   = t1 * inv;
                float rstd2 = rsqrtf(fmaf(-mu2, mu2, tq * inv) + 1e-5f);
                float logit = fmaf(rstd2, fmaf(-mu2, gsum, t3), ccst);
                g_logits[((int*)sm)[SOF + ecol]] = logit;
            }
    }
}

// ---------------------------------------------------------------------------
// Kernel 3: argmax with lazy exact-fp32 rescue of near-ties (window 0.06)
// ---------------------------------------------------------------------------
static constexpr float CAND_WIN = 0.06f;

__global__ __launch_bounds__(256) void argmax_kernel(
    const float* __restrict__ gumbel, float* __restrict__ out)
{
    __shared__ float sLog[NN];
    __shared__ float sSel[NN];
    __shared__ float sZ[NS * NN];
    __shared__ float sVc[NS * 64];
    __shared__ int   sCand[NS * 32];

    const int k = blockIdx.x;
    const int b = blockIdx.y;
    const int r = k + NT;
    const int nsrc = r;
    const int tid = threadIdx.x;
    const int wid = tid >> 5, lane = tid & 31;

    for (int c = tid; c < NN; c += 256) sSel[c] = 0.f;
    for (int c = tid; c < nsrc; c += 256)
        sLog[c] = g_logits[((size_t)b * NT + k) * NN + c];
    __syncthreads();

    if (wid < NS) {
        const float* gu = gumbel + (((size_t)wid * NB + b) * NT + k) * NSRC;
        const float NEGINF = -__int_as_float(0x7f800000);

        float best[4];
#pragma unroll
        for (int q = 0; q < 4; ++q) best[q] = NEGINF;
        for (int c0 = lane; c0 < nsrc; c0 += 128) {
#pragma unroll
            for (int q = 0; q < 4; ++q) {
                int cc = c0 + 32 * q;
                if (cc < nsrc) {
                    float z = sLog[cc] + gu[cc];
                    sZ[wid * NN + cc] = z;
                    best[q] = fmaxf(best[q], z);
                }
            }
        }
        float m = fmaxf(fmaxf(best[0], best[1]), fmaxf(best[2], best[3]));
#pragma unroll
        for (int off = 16; off; off >>= 1)
            m = fmaxf(m, __shfl_xor_sync(0xffffffffu, m, off));
        const float thr = m - CAND_WIN;
        __syncwarp();

        int cnt = 0;
        for (int c0 = 0; c0 < nsrc; c0 += 32) {
            int cc = c0 + lane;
            float z = (cc < nsrc) ? sZ[wid * NN + cc] : NEGINF;
            unsigned msk = __ballot_sync(0xffffffffu, z >= thr);
            if (lane == 0) {
                while (msk) {
                    int bit = __ffs(msk) - 1;
                    if (cnt < 32) sCand[wid * 32 + cnt] = c0 + bit;
                    ++cnt;
                    msk &= msk - 1;
                }
            }
        }
        cnt = __shfl_sync(0xffffffffu, cnt, 0);
        if (cnt > 32) cnt = 32;
        __syncwarp();

        int sel = sCand[wid * 32];
        if (cnt > 1) {
            // exact rescoring; weights/P read straight from global (rare path)
            const float p0 = g_P[((size_t)b * NN + r) * 64 + lane];
            const float p1 = g_P[((size_t)b * NN + r) * 64 + 32 + lane];
            float bz = NEGINF;
            for (int q = 0; q < cnt; ++q) {
                int cc = sCand[wid * 32 + q];
                float q0 = g_Qt[((size_t)b * 64 + lane) * NN + cc];
                float q1 = g_Qt[((size_t)b * 64 + lane + 32) * NN + cc];
                float v0 = fmaxf(p0 + q0, 0.f);
                float v1 = fmaxf(p1 + q1, 0.f);
                sVc[wid * 64 + lane] = v0;
                sVc[wid * 64 + lane + 32] = v1;
                float s1 = v0 + v1;
                float s2 = fmaf(v0, v0, v1 * v1);
#pragma unroll
                for (int off = 16; off; off >>= 1) {
                    s1 += __shfl_xor_sync(0xffffffffu, s1, off);
                    s2 += __shfl_xor_sync(0xffffffffu, s2, off);
                }
                const float inv = 1.f / 64.f;
                float mu   = s1 * inv;
                float rstd = rsqrtf(fmaf(-mu, mu, s2 * inv) + 1e-5f);
                __syncwarp();
                float a0 = 0.f, a1 = 0.f;
#pragma unroll 8
                for (int j = 0; j < 64; ++j) {
                    float vv = sVc[wid * 64 + j];
                    a0 = fmaf(vv, g_W2f[j * 64 + lane], a0);
                    a1 = fmaf(vv, g_W2f[j * 64 + lane + 32], a1);
                }
                float mur = mu * rstd;
                float h0 = fmaxf(fmaf(rstd, a0, fmaf(-mur, g_Go[lane], g_Co[lane])), 0.f);
                float h1 = fmaxf(fmaf(rstd, a1, fmaf(-mur, g_Go[lane + 32], g_Co[lane + 32])), 0.f);
                float S1 = h0 + h1;
                float Sq = fmaf(h0, h0, h1 * h1);
                float S3 = fmaf(h0, g_Gw[lane], h1 * g_Gw[lane + 32]);
#pragma unroll
                for (int off = 16; off; off >>= 1) {
                    S1 += __shfl_xor_sync(0xffffffffu, S1, off);
                    Sq += __shfl_xor_sync(0xffffffffu, Sq, off);
                    S3 += __shfl_xor_sync(0xffffffffu, S3, off);
                }
                float mu2   = S1 * inv;
                float rstd2 = rsqrtf(fmaf(-mu2, mu2, Sq * inv) + 1e-5f);
                float lg    = fmaf(rstd2, fmaf(-mu2, g_scal[0], S3), g_scal[1]);
                float z     = lg + __ldg(&gu[cc]);
                if (z > bz) { bz = z; sel = cc; }
                __syncwarp();
            }
        }
        if (lane == 0) sSel[sel] = 1.f;
    }
    __syncthreads();

    float* rowR = out + ((size_t)b * NN + r) * NN;
    float* rowK = out + ((size_t)b * NN + k) * NN;
    for (int c = tid; c < NN; c += 256) {
        rowR[c] = sSel[c];
        rowK[c] = 0.f;
    }
}

// ---------------------------------------------------------------------------
extern "C" void kernel_launch(void* const* d_in, const int* in_sizes, int n_in,
                              void* d_out, int out_size) {
    const float* nodes  = (const float*)d_in[0];
    const float* w1     = (const float*)d_in[1];
    const float* b1     = (const float*)d_in[2];
    const float* g1     = (const float*)d_in[3];
    const float* be1    = (const float*)d_in[4];
    const float* w2     = (const float*)d_in[5];
    const float* b2     = (const float*)d_in[6];
    const float* g2     = (const float*)d_in[7];
    const float* be2    = (const float*)d_in[8];
    const float* w3     = (const float*)d_in[9];
    const float* b3     = (const float*)d_in[10];
    const float* gumbel = (const float*)d_in[11];

    cudaFuncSetAttribute(mlp_kernel,
                         cudaFuncAttributeMaxDynamicSharedMemorySize, SMEM_BYTES);

    setup_kernel<<<1, 1024>>>(w2, g1, be1, b2, g2, be2, w3, b3);
    proj_kernel<<<NB * NN / 16, 256>>>(nodes, w1, b1);
    mlp_kernel<<<NBLK, 256, SMEM_BYTES>>>();
    dim3 grid3(NT, NB);
    argmax_kernel<<<grid3, 256>>>(gumbel, (float*)d_out);
}

// round 11
// speedup vs baseline: 1.0231x; 1.0151x over previous
#include <cuda_runtime.h>
#include <cstdint>

static constexpr int NB   = 8;
static constexpr int NN   = 384;
static constexpr int NF   = 64;
static constexpr int NT   = 192;
static constexpr int NS   = 5;
static constexpr int NSRC = 383;
static constexpr int NE   = 55200;
static constexpr int ETOT = NB * NE;        // 441600
static constexpr int CH   = 128;
static constexpr int NBLK = ETOT / CH;      // 3450

static constexpr int VSTR = 136;            // conflict-free B-fragment stride
static constexpr float CAND_WIN = 0.06f;

// ---------------- global scratch ----------------
__device__ float g_P [NB * NN * NF];        // [b][n][f]
__device__ float g_Q [NB * NN * NF];        // [b][n][f] (row-major source proj)
__device__ float g_Qt[NB * NF * NN];        // [b][f][n] (transposed, for mlp)
__device__ float g_logits[NB * NT * NN];
__device__ float g_Whi[4096];               // tf32 A-fragments
__device__ float g_W2f[4096];               // g1-folded W2 [j][o]
__device__ float g_Go[64], g_Co[64], g_Gw[64];
__device__ float g_scal[2];
__device__ unsigned g_selbits[NB * NT * 12];   // 384-bit per (b,k)

__device__ __forceinline__ float tf32r(float x) {
    uint32_t u;
    asm("cvt.rna.tf32.f32 %0, %1;" : "=r"(u) : "f"(x));
    return __uint_as_float(u);
}

#define MMA_TF32(dd, av, b0, b1) \
    asm volatile("mma.sync.aligned.m16n8k8.row.col.f32.tf32.tf32.f32 " \
        "{%0,%1,%2,%3}, {%4,%5,%6,%7}, {%8,%9}, {%0,%1,%2,%3};" \
        : "+f"((dd)[0]), "+f"((dd)[1]), "+f"((dd)[2]), "+f"((dd)[3]) \
        : "r"(__float_as_uint((av).x)), "r"(__float_as_uint((av).y)), \
          "r"(__float_as_uint((av).z)), "r"(__float_as_uint((av).w)), \
          "r"(b0), "r"(b1))

#define ROWOFF(kk) ((kk) * 192 + (((kk) * ((kk) - 1)) >> 1))

// ---------------------------------------------------------------------------
// Kernel 0: constants + bitmap zero
// ---------------------------------------------------------------------------
__global__ void setup_kernel(const float* __restrict__ w2,
                             const float* __restrict__ g1,
                             const float* __restrict__ be1,
                             const float* __restrict__ b2,
                             const float* __restrict__ g2,
                             const float* __restrict__ be2,
                             const float* __restrict__ w3,
                             const float* __restrict__ b3) {
    int t = threadIdx.x;                  // 0..1023
    int s = t >> 7, om = (t >> 5) & 3, lane = t & 31;
    int g = lane >> 2, tig = lane & 3;
    int o1 = om * 16 + g, o2 = o1 + 8;
    int j1 = 8 * s + tig, j2 = j1 + 4;
    g_Whi[t * 4 + 0] = tf32r(g1[j1] * w2[j1 * 64 + o1]);
    g_Whi[t * 4 + 1] = tf32r(g1[j1] * w2[j1 * 64 + o2]);
    g_Whi[t * 4 + 2] = tf32r(g1[j2] * w2[j2 * 64 + o1]);
    g_Whi[t * 4 + 3] = tf32r(g1[j2] * w2[j2 * 64 + o2]);
#pragma unroll
    for (int q = 0; q < 4; ++q) {
        int i = t * 4 + q;                // [j][o]
        g_W2f[i] = g1[i >> 6] * w2[i];
    }
    for (int i = t; i < NB * NT * 12; i += 1024) g_selbits[i] = 0u;
    if (t < 64) {
        float G = 0.f, C = b2[t];
        for (int j = 0; j < 64; ++j) {
            G += g1[j] * w2[j * 64 + t];
            C = fmaf(be1[j], w2[j * 64 + t], C);
        }
        g_Go[t] = G;
        g_Co[t] = C;
        g_Gw[t] = g2[t] * w3[t];
    }
    if (t == 0) {
        float gs = 0.f, cc = b3[0];
        for (int o = 0; o < 64; ++o) { gs += g2[o] * w3[o]; cc = fmaf(be2[o], w3[o], cc); }
        g_scal[0] = gs;
        g_scal[1] = cc;
    }
}

// ---------------------------------------------------------------------------
// Kernel 1: projection (also stores row-major Q for coalesced refine)
// ---------------------------------------------------------------------------
__global__ __launch_bounds__(256) void proj_kernel(const float* __restrict__ nodes,
                                                   const float* __restrict__ w1,
                                                   const float* __restrict__ b1) {
    __shared__ float sW[128 * 64];
    __shared__ float sNd[16 * 64];
    const int tid = threadIdx.x;
    for (int i = tid; i < 128 * 64; i += 256) sW[i] = w1[i];
    const int n0 = blockIdx.x * 16;
    for (int i = tid; i < 16 * 64; i += 256) sNd[i] = nodes[n0 * 64 + i];
    __syncthreads();

    const int nl = tid >> 4;
    const int og = tid & 15;
    const bool isP = og < 8;
    const int colb = (og & 7) * 8;

    float acc[8];
#pragma unroll
    for (int i = 0; i < 8; ++i) acc[i] = 0.f;
    const float* nd = &sNd[nl * 64];
    const float* wp = sW + (isP ? 0 : 64 * 64) + colb;
#pragma unroll 16
    for (int f = 0; f < 64; ++f) {
        float x = nd[f];
        const float4* w4 = (const float4*)(wp + f * 64);
        float4 a = w4[0], bq = w4[1];
        acc[0] = fmaf(x, a.x, acc[0]);  acc[1] = fmaf(x, a.y, acc[1]);
        acc[2] = fmaf(x, a.z, acc[2]);  acc[3] = fmaf(x, a.w, acc[3]);
        acc[4] = fmaf(x, bq.x, acc[4]); acc[5] = fmaf(x, bq.y, acc[5]);
        acc[6] = fmaf(x, bq.z, acc[6]); acc[7] = fmaf(x, bq.w, acc[7]);
    }
    const int gn = n0 + nl;
    if (isP) {
#pragma unroll
        for (int i = 0; i < 8; ++i)
            g_P[gn * 64 + colb + i] = acc[i] + b1[colb + i];
    } else {
        const int bb = gn / NN, n = gn % NN;
#pragma unroll
        for (int i = 0; i < 8; ++i) {
            g_Q[gn * 64 + colb + i] = acc[i];
            g_Qt[((size_t)bb * 64 + colb + i) * NN + n] = acc[i];
        }
    }
}

// ---------------------------------------------------------------------------
// Kernel 2: edge MLP — single-pass TF32 mma.sync (R7 structure, unchanged)
// ---------------------------------------------------------------------------
static constexpr int SVH = 0;
static constexpr int SRS = SVH + 64 * VSTR;
static constexpr int SMU = SRS + 128;
static constexpr int SP1 = SMU + 128;
static constexpr int SP2 = SP1 + 128;
static constexpr int SR1 = SP2 + 128;
static constexpr int SRQ = SR1 + 128;
static constexpr int SR3 = SRQ + 128;
static constexpr int SGO = SR3 + 128;
static constexpr int SCO = SGO + 64;
static constexpr int SGW = SCO + 64;
static constexpr int SOF = SGW + 64;
static constexpr int SSC = SOF + 128;
static constexpr int SMEM_FLOATS = SSC + 2;
static constexpr int SMEM_BYTES = SMEM_FLOATS * 4;

__global__ __launch_bounds__(256, 3) void mlp_kernel() {
    extern __shared__ float sm[];
    const int tid  = threadIdx.x;
    const int lane = tid & 31;
    const int wid  = tid >> 5;

    if (tid < 64) {
        sm[SGO + tid] = g_Go[tid];
        sm[SCO + tid] = g_Co[tid];
        sm[SGW + tid] = g_Gw[tid];
    }
    if (tid == 0) { sm[SSC] = g_scal[0]; sm[SSC + 1] = g_scal[1]; }

    const int el = tid & 127;
    const int kh = tid >> 7;
    const int k0 = kh * 32;
    const int E  = blockIdx.x * CH + el;
    const int b  = E / NE;
    const int eb = E - b * NE;
    int k = (int)floorf(-191.5f + sqrtf(36672.25f + 2.0f * (float)eb));
    k = max(0, min(NT - 1, k));
    while (k < NT - 1 && ROWOFF(k + 1) <= eb) ++k;
    while (k > 0 && ROWOFF(k) > eb) --k;
    const int c = eb - ROWOFF(k);
    const int r = k + NT;
    if (kh == 0) ((int*)sm)[SOF + el] = (b * NT + k) * NN + c;

    {
        const float* pp = g_P + ((size_t)(b * NN + r)) * 64 + k0;
        const float* qp = g_Qt + ((size_t)(b * 64 + k0)) * NN + c;
        float pv[32];
        const float4* p4 = (const float4*)pp;
#pragma unroll
        for (int i = 0; i < 8; ++i) {
            float4 t4 = p4[i];
            pv[4 * i] = t4.x; pv[4 * i + 1] = t4.y; pv[4 * i + 2] = t4.z; pv[4 * i + 3] = t4.w;
        }
        float s1 = 0.f, s2 = 0.f;
#pragma unroll
        for (int j = 0; j < 32; ++j) {
            float v = fmaxf(pv[j] + qp[j * NN], 0.f);
            s1 += v;
            s2 = fmaf(v, v, s2);
            sm[SVH + (k0 + j) * VSTR + el] = tf32r(v);
        }
        if (kh) { sm[SP1 + el] = s1; sm[SP2 + el] = s2; }
        __syncthreads();
        if (!kh) {
            s1 += sm[SP1 + el];
            s2 += sm[SP2 + el];
            const float inv = 1.f / 64.f;
            float mu   = s1 * inv;
            float rstd = rsqrtf(fmaf(-mu, mu, s2 * inv) + 1e-5f);
            sm[SRS + el] = rstd;
            sm[SMU + el] = mu * rstd;
        }
    }
    __syncthreads();

    const int g     = lane >> 2;
    const int tig   = lane & 3;
    const int ohalf = wid >> 2;
    const int eb0   = (wid & 3) * 32;

    float d[2][4][4];
#pragma unroll
    for (int mt = 0; mt < 2; ++mt)
#pragma unroll
        for (int nt = 0; nt < 4; ++nt)
#pragma unroll
            for (int q = 0; q < 4; ++q) d[mt][nt][q] = 0.f;

    const float4* WH = (const float4*)g_Whi;

#pragma unroll
    for (int s = 0; s < 8; ++s) {
        const int row0 = (8 * s + tig) * VSTR;
        const int row1 = row0 + 4 * VSTR;
        uint32_t b0[4], b1[4];
#pragma unroll
        for (int nt = 0; nt < 4; ++nt) {
            int col = eb0 + nt * 8 + g;
            b0[nt] = __float_as_uint(sm[SVH + row0 + col]);
            b1[nt] = __float_as_uint(sm[SVH + row1 + col]);
        }
        float4 ah0 = WH[(s * 4 + ohalf * 2 + 0) * 32 + lane];
        float4 ah1 = WH[(s * 4 + ohalf * 2 + 1) * 32 + lane];
#pragma unroll
        for (int nt = 0; nt < 4; ++nt) {
            MMA_TF32(d[0][nt], ah0, b0[nt], b1[nt]);
            MMA_TF32(d[1][nt], ah1, b0[nt], b1[nt]);
        }
    }

    const int ob = ohalf * 32;
    const float Go0 = sm[SGO + ob + g],      Co0 = sm[SCO + ob + g],      Gw0 = sm[SGW + ob + g];
    const float Go1 = sm[SGO + ob + g + 8],  Co1 = sm[SCO + ob + g + 8],  Gw1 = sm[SGW + ob + g + 8];
    const float Go2 = sm[SGO + ob + g + 16], Co2 = sm[SCO + ob + g + 16], Gw2 = sm[SGW + ob + g + 16];
    const float Go3 = sm[SGO + ob + g + 24], Co3 = sm[SCO + ob + g + 24], Gw3 = sm[SGW + ob + g + 24];

    float S1[4][2], SQ[4][2], S3[4][2];
#pragma unroll
    for (int nt = 0; nt < 4; ++nt)
#pragma unroll
        for (int h = 0; h < 2; ++h) {
            int ecol = eb0 + nt * 8 + 2 * tig + h;
            float rstd = sm[SRS + ecol];
            float mur  = sm[SMU + ecol];
            float h0 = fmaxf(fmaf(d[0][nt][h],     rstd, fmaf(-mur, Go0, Co0)), 0.f);
            float h1 = fmaxf(fmaf(d[0][nt][2 + h], rstd, fmaf(-mur, Go1, Co1)), 0.f);
            float h2 = fmaxf(fmaf(d[1][nt][h],     rstd, fmaf(-mur, Go2, Co2)), 0.f);
            float h3 = fmaxf(fmaf(d[1][nt][2 + h], rstd, fmaf(-mur, Go3, Co3)), 0.f);
            S1[nt][h] = h0 + h1 + h2 + h3;
            SQ[nt][h] = fmaf(h0, h0, fmaf(h1, h1, fmaf(h2, h2, h3 * h3)));
            S3[nt][h] = fmaf(h0, Gw0, fmaf(h1, Gw1, fmaf(h2, Gw2, h3 * Gw3)));
        }

#pragma unroll
    for (int m = 4; m <= 16; m <<= 1) {
#pragma unroll
        for (int nt = 0; nt < 4; ++nt)
#pragma unroll
            for (int h = 0; h < 2; ++h) {
                S1[nt][h] += __shfl_xor_sync(0xffffffffu, S1[nt][h], m);
                SQ[nt][h] += __shfl_xor_sync(0xffffffffu, SQ[nt][h], m);
                S3[nt][h] += __shfl_xor_sync(0xffffffffu, S3[nt][h], m);
            }
    }

    if (ohalf == 0 && g == 0) {
#pragma unroll
        for (int nt = 0; nt < 4; ++nt)
#pragma unroll
            for (int h = 0; h < 2; ++h) {
                int ecol = eb0 + nt * 8 + 2 * tig + h;
                sm[SR1 + ecol] = S1[nt][h];
                sm[SRQ + ecol] = SQ[nt][h];
                sm[SR3 + ecol] = S3[nt][h];
            }
    }
    __syncthreads();
    if (ohalf == 1 && g == 0) {
        const float gsum = sm[SSC], ccst = sm[SSC + 1];
        const float inv = 1.f / 64.f;
#pragma unroll
        for (int nt = 0; nt < 4; ++nt)
#pragma unroll
            for (int h = 0; h < 2; ++h) {
                int ecol = eb0 + nt * 8 + 2 * tig + h;
                float t1 = S1[nt][h] + sm[SR1 + ecol];
                float tq = SQ[nt][h] + sm[SRQ + ecol];
                float t3 = S3[nt][h] + sm[SR3 + ecol];
                float mu2   = t1 * inv;
                float rstd2 = rsqrtf(fmaf(-mu2, mu2, tq * inv) + 1e-5f);
                float logit = fmaf(rstd2, fmaf(-mu2, gsum, t3), ccst);
                g_logits[((int*)sm)[SOF + ecol]] = logit;
            }
    }
}

// ---------------------------------------------------------------------------
// Kernel 3: warp-per-(s,b,k) select; exact refine on near-ties; bitmap out
// ---------------------------------------------------------------------------
__global__ __launch_bounds__(256) void select_kernel(const float* __restrict__ gumbel) {
    const int w    = (blockIdx.x * 256 + threadIdx.x) >> 5;   // 0..7679
    const int lane = threadIdx.x & 31;
    const int s    = w / (NB * NT);
    const int rem  = w - s * (NB * NT);
    const int b    = rem / NT;
    const int k    = rem - b * NT;
    const int r    = k + NT;
    const int nsrc = r;

    const float* lg = g_logits + ((size_t)b * NT + k) * NN;
    const float* gu = gumbel + (((size_t)s * NB + b) * NT + k) * NSRC;
    const float NEGINF = -__int_as_float(0x7f800000);

    // pass 1: z in registers, 4 rotating max-chains with index
    float z[12];
    float bv[4]; int bx[4];
#pragma unroll
    for (int q = 0; q < 4; ++q) { bv[q] = NEGINF; bx[q] = 0x7fffffff; }
#pragma unroll
    for (int i = 0; i < 12; ++i) {
        int cc = i * 32 + lane;
        float zz = (cc < nsrc) ? lg[cc] + gu[cc] : NEGINF;
        z[i] = zz;
        int q = i & 3;
        if (zz > bv[q]) { bv[q] = zz; bx[q] = cc; }
    }
    float mv = bv[0]; int mx = bx[0];
#pragma unroll
    for (int q = 1; q < 4; ++q)
        if (bv[q] > mv || (bv[q] == mv && bx[q] < mx)) { mv = bv[q]; mx = bx[q]; }
#pragma unroll
    for (int off = 16; off; off >>= 1) {
        float ov = __shfl_xor_sync(0xffffffffu, mv, off);
        int   oi = __shfl_xor_sync(0xffffffffu, mx, off);
        if (ov > mv || (ov == mv && oi < mx)) { mv = ov; mx = oi; }
    }
    const float thr = mv - CAND_WIN;

    // candidate ballots from registers
    unsigned ball[12];
    int cnt = 0;
#pragma unroll
    for (int i = 0; i < 12; ++i) {
        ball[i] = __ballot_sync(0xffffffffu, z[i] >= thr);
        cnt += __popc(ball[i]);
    }

    int sel = mx;
    if (cnt > 1) {
        // exact fp32 rescoring, coalesced loads, shuffles for broadcast
        const float* Pp = g_P + ((size_t)b * NN + r) * 64;
        const float p0 = Pp[lane], p1 = Pp[lane + 32];
        const float inv = 1.f / 64.f;
        float bz = NEGINF;
        sel = 0x7fffffff;
        for (int i = 0; i < 12; ++i) {
            unsigned mk = ball[i];
            while (mk) {
                int bit = __ffs(mk) - 1;
                mk &= mk - 1;
                int cc = i * 32 + bit;
                const float* Qp = g_Q + ((size_t)b * NN + cc) * 64;
                float v0 = fmaxf(p0 + Qp[lane], 0.f);
                float v1 = fmaxf(p1 + Qp[lane + 32], 0.f);
                float s1 = v0 + v1;
                float s2 = fmaf(v0, v0, v1 * v1);
#pragma unroll
                for (int off = 16; off; off >>= 1) {
                    s1 += __shfl_xor_sync(0xffffffffu, s1, off);
                    s2 += __shfl_xor_sync(0xffffffffu, s2, off);
                }
                float mu   = s1 * inv;
                float rstd = rsqrtf(fmaf(-mu, mu, s2 * inv) + 1e-5f);
                float a0 = 0.f, a1 = 0.f;
#pragma unroll 8
                for (int j = 0; j < 32; ++j) {
                    float vv0 = __shfl_sync(0xffffffffu, v0, j);
                    float vv1 = __shfl_sync(0xffffffffu, v1, j);
                    a0 = fmaf(vv0, g_W2f[j * 64 + lane], a0);
                    a0 = fmaf(vv1, g_W2f[(j + 32) * 64 + lane], a0);
                    a1 = fmaf(vv0, g_W2f[j * 64 + lane + 32], a1);
                    a1 = fmaf(vv1, g_W2f[(j + 32) * 64 + lane + 32], a1);
                }
                float mur = mu * rstd;
                float h0 = fmaxf(fmaf(rstd, a0, fmaf(-mur, g_Go[lane], g_Co[lane])), 0.f);
                float h1 = fmaxf(fmaf(rstd, a1, fmaf(-mur, g_Go[lane + 32], g_Co[lane + 32])), 0.f);
                float S1 = h0 + h1;
                float Sq = fmaf(h0, h0, h1 * h1);
                float S3 = fmaf(h0, g_Gw[lane], h1 * g_Gw[lane + 32]);
#pragma unroll
                for (int off = 16; off; off >>= 1) {
                    S1 += __shfl_xor_sync(0xffffffffu, S1, off);
                    Sq += __shfl_xor_sync(0xffffffffu, Sq, off);
                    S3 += __shfl_xor_sync(0xffffffffu, S3, off);
                }
                float mu2   = S1 * inv;
                float rstd2 = rsqrtf(fmaf(-mu2, mu2, Sq * inv) + 1e-5f);
                float lgx   = fmaf(rstd2, fmaf(-mu2, g_scal[0], S3), g_scal[1]);
                float zz    = lgx + gu[cc];
                if (zz > bz) { bz = zz; sel = cc; }   // ascending order -> first idx on ties
            }
        }
    }
    if (lane == 0)
        atomicOr(&g_selbits[(b * NT + k) * 12 + (sel >> 5)], 1u << (sel & 31));
}

// ---------------------------------------------------------------------------
// Kernel 4: expand bitmap -> output rows
// ---------------------------------------------------------------------------
__global__ __launch_bounds__(128) void write_kernel(float* __restrict__ out) {
    const int k = blockIdx.x;
    const int b = blockIdx.y;
    const int r = k + NT;
    const int tid = threadIdx.x;
    const unsigned* bits = &g_selbits[(b * NT + k) * 12];

    float* rowR = out + ((size_t)b * NN + r) * NN;
    float* rowK = out + ((size_t)b * NN + k) * NN;
#pragma unroll
    for (int i = 0; i < 3; ++i) {
        int c = i * 128 + tid;
        rowR[c] = (bits[c >> 5] >> (c & 31)) & 1u ? 1.0f : 0.0f;
        rowK[c] = 0.0f;
    }
}

// ---------------------------------------------------------------------------
extern "C" void kernel_launch(void* const* d_in, const int* in_sizes, int n_in,
                              void* d_out, int out_size) {
    const float* nodes  = (const float*)d_in[0];
    const float* w1     = (const float*)d_in[1];
    const float* b1     = (const float*)d_in[2];
    const float* g1     = (const float*)d_in[3];
    const float* be1    = (const float*)d_in[4];
    const float* w2     = (const float*)d_in[5];
    const float* b2     = (const float*)d_in[6];
    const float* g2     = (const float*)d_in[7];
    const float* be2    = (const float*)d_in[8];
    const float* w3     = (const float*)d_in[9];
    const float* b3     = (const float*)d_in[10];
    const float* gumbel = (const float*)d_in[11];

    cudaFuncSetAttribute(mlp_kernel,
                         cudaFuncAttributeMaxDynamicSharedMemorySize, SMEM_BYTES);

    setup_kernel<<<1, 1024>>>(w2, g1, be1, b2, g2, be2, w3, b3);
    proj_kernel<<<NB * NN / 16, 256>>>(nodes, w1, b1);
    mlp_kernel<<<NBLK, 256, SMEM_BYTES>>>();
    select_kernel<<<NS * NB * NT / 8, 256>>>(gumbel);
    dim3 grid4(NT, NB);
    write_kernel<<<grid4, 128>>>((float*)d_out);
}